// round 4
// baseline (speedup 1.0000x reference)
#include <cuda_runtime.h>
#include <math.h>

// ---------------------------------------------------------------------------
// Problem constants
// ---------------------------------------------------------------------------
namespace {
constexpr int kC = 32, kG = 8, kD = 32, kH = 192, kW = 192;
constexpr int kHW = kH * kW;
constexpr int kNS = 4;   // nsrc = V-1

// output layout (concatenated tuple, all f32)
constexpr int OFF_DEPTH = 0;
constexpr int OFF_CONF  = OFF_DEPTH + kHW;
constexpr int OFF_ATTN  = OFF_CONF + kHW;            // (D,H,W)
constexpr int OFF_EN    = OFF_ATTN + kD * kHW;       // (3,H,W)
constexpr int OFF_SW    = OFF_EN + 3 * kHW;          // (H,W)
constexpr int OFF_WT    = OFF_SW + kHW;              // (NS,H,W)
constexpr int OFF_NV    = OFF_WT + kNS * kHW;        // (D,H,W)
constexpr int OFF_MIN   = OFF_NV + kD * kHW;         // (H,W)
constexpr int OFF_MAX   = OFF_MIN + kHW;             // (H,W)
}

// ---------------------------------------------------------------------------
// Scratch (static __device__ arrays: no allocation allowed)
// ---------------------------------------------------------------------------
__device__ float g_ref_t[kHW * kC];              // ref features (H,W,C)
__device__ float g_src_t[kNS * kHW * kC];        // src features (ns,H,W,C)
__device__ float g_rot[kNS * 9];
__device__ float g_trans[kNS * 3];
__device__ float g_norv[kNS * 3];
__device__ unsigned g_min_enc, g_max_enc;

// order-preserving float<->uint encoding (for atomic min/max)
__device__ __forceinline__ unsigned enc_f(float x) {
    unsigned u = __float_as_uint(x);
    return (u & 0x80000000u) ? ~u : (u | 0x80000000u);
}
__device__ __forceinline__ float dec_f(unsigned u) {
    return (u & 0x80000000u) ? __uint_as_float(u & 0x7FFFFFFFu)
                             : __uint_as_float(~u);
}

// ---------------------------------------------------------------------------
// Setup: projection matrices, relative rotations, min/max init (1 thread)
// ---------------------------------------------------------------------------
__device__ void inv3(const double* a, double* o) {
    double c00 =   a[4]*a[8] - a[5]*a[7];
    double c01 = -(a[3]*a[8] - a[5]*a[6]);
    double c02 =   a[3]*a[7] - a[4]*a[6];
    double det = a[0]*c00 + a[1]*c01 + a[2]*c02;
    double id = 1.0 / det;
    o[0] =  c00 * id;
    o[1] = -(a[1]*a[8] - a[2]*a[7]) * id;
    o[2] =  (a[1]*a[5] - a[2]*a[4]) * id;
    o[3] =  c01 * id;
    o[4] =  (a[0]*a[8] - a[2]*a[6]) * id;
    o[5] = -(a[0]*a[5] - a[2]*a[3]) * id;
    o[6] =  c02 * id;
    o[7] = -(a[0]*a[7] - a[1]*a[6]) * id;
    o[8] =  (a[0]*a[4] - a[1]*a[3]) * id;
}
__device__ void mm3(const double* a, const double* b, double* o) {
    for (int r = 0; r < 3; r++)
        for (int c = 0; c < 3; c++)
            o[r*3+c] = a[r*3]*b[c] + a[r*3+1]*b[3+c] + a[r*3+2]*b[6+c];
}

__global__ void setup_kernel(const float* __restrict__ rotation,
                             const float* __restrict__ proj) {
    if (threadIdx.x != 0 || blockIdx.x != 0) return;
    g_min_enc = 0xFFFFFFFFu;
    g_max_enc = 0u;
    // proj layout: (1, 5, 2, 4, 4) : [view][E|K][4][4]
    // M_v = K33 @ E33 ; t_v = K33 @ E[:3,3]
    double M[5][9], t[5][3];
    for (int v = 0; v < 5; v++) {
        const float* E = proj + v * 32;
        const float* K = proj + v * 32 + 16;
        for (int r = 0; r < 3; r++) {
            for (int c = 0; c < 3; c++) {
                double s = 0.0;
                for (int k = 0; k < 3; k++) s += (double)K[r*4+k] * (double)E[k*4+c];
                M[v][r*3+c] = s;
            }
            double s = 0.0;
            for (int k = 0; k < 3; k++) s += (double)K[r*4+k] * (double)E[k*4+3];
            t[v][r] = s;
        }
    }
    double MrI[9]; inv3(M[0], MrI);
    double R0[9];  for (int i = 0; i < 9; i++) R0[i] = (double)rotation[i];
    double R0I[9]; inv3(R0, R0I);
    for (int s = 0; s < kNS; s++) {
        int v = s + 1;
        // proj = src_new @ inv(ref_new): rot = Ms Mr^-1, trans = ts - rot tr
        double R[9]; mm3(M[v], MrI, R);
        for (int i = 0; i < 9; i++) g_rot[s*9+i] = (float)R[i];
        for (int r = 0; r < 3; r++) {
            double tr = t[v][r];
            for (int c = 0; c < 3; c++) tr -= R[r*3+c] * t[0][c];
            g_trans[s*3+r] = (float)tr;
        }
        // norv = row 2 of (R_v @ R_0^-1)
        double Rv[9]; for (int i = 0; i < 9; i++) Rv[i] = (double)rotation[v*9+i];
        double Rel[9]; mm3(Rv, R0I, Rel);
        for (int c = 0; c < 3; c++) g_norv[s*3+c] = (float)Rel[6+c];
    }
}

// ---------------------------------------------------------------------------
// Transpose features (C,H,W) -> (H,W,C), 5 views. Coalesced both sides.
// ---------------------------------------------------------------------------
__global__ void transpose_kernel(const float* __restrict__ ref,
                                 const float* __restrict__ src) {
    __shared__ float tile[32][33];
    int v = blockIdx.z;
    const float* in = (v == 0) ? ref : (src + (size_t)(v - 1) * kC * kHW);
    float* out = (v == 0) ? g_ref_t : (g_src_t + (size_t)(v - 1) * kHW * kC);
    int wbase = blockIdx.x * 32;
    int h = blockIdx.y;
    int tx = threadIdx.x, ty = threadIdx.y;   // ty = channel on read
    tile[ty][tx] = in[(size_t)ty * kHW + h * kW + wbase + tx];
    __syncthreads();
    out[(size_t)(h * kW + wbase + ty) * kC + tx] = tile[tx][ty];
}

// ---------------------------------------------------------------------------
// hmin / hmax reduction over depth_hypo
// ---------------------------------------------------------------------------
__global__ void minmax_kernel(const float* __restrict__ dh) {
    __shared__ unsigned smn[256], smx[256];
    unsigned lmn = 0xFFFFFFFFu, lmx = 0u;
    for (int i = blockIdx.x * blockDim.x + threadIdx.x; i < kD * kHW;
         i += gridDim.x * blockDim.x) {
        unsigned e = enc_f(dh[i]);
        lmn = min(lmn, e);
        lmx = max(lmx, e);
    }
    smn[threadIdx.x] = lmn; smx[threadIdx.x] = lmx;
    __syncthreads();
    for (int s = 128; s > 0; s >>= 1) {
        if (threadIdx.x < s) {
            smn[threadIdx.x] = min(smn[threadIdx.x], smn[threadIdx.x + s]);
            smx[threadIdx.x] = max(smx[threadIdx.x], smx[threadIdx.x + s]);
        }
        __syncthreads();
    }
    if (threadIdx.x == 0) {
        atomicMin(&g_min_enc, smn[0]);
        atomicMax(&g_max_enc, smx[0]);
    }
}

// ---------------------------------------------------------------------------
// Main fused kernel: one warp per pixel, lane = channel (C=32), D=32=warpSize
// ---------------------------------------------------------------------------
__global__ __launch_bounds__(128, 3) void main_kernel(
    const float* __restrict__ normal_plane,
    const float* __restrict__ depth_hypo,
    const float* __restrict__ w_reg,
    const float* __restrict__ w_norm,
    float* __restrict__ out)
{
    const unsigned FULL = 0xFFFFFFFFu;
    int p = blockIdx.x * 4 + (threadIdx.x >> 5);
    int lane = threadIdx.x & 31;
    float xf = (float)(p % kW), yf = (float)(p / kW);

    float refc = g_ref_t[(size_t)p * kC + lane];            // ref feature, my channel
    float np0 = normal_plane[p];
    float np1 = normal_plane[kHW + p];
    float np2 = normal_plane[2 * kHW + p];
    float wreg_g = w_reg[lane >> 2];
    float dep_lane = depth_hypo[lane * kHW + p];            // lane l holds depth l

    float cfacc[kD];                                        // cor_feats[g(lane), d]
#pragma unroll
    for (int d = 0; d < kD; d++) cfacc[d] = 0.f;
    float cws_lane  = 1e-8f;   // cor_weight_sum[d=lane]
    float sumw_lane = 1e-8f;   // sum_weight[d=lane]
    float nv_lane   = 0.f;     // num_valid[d=lane]

#pragma unroll 1
    for (int s = 0; s < kNS; s++) {
        const float* srcT = g_src_t + (size_t)s * (kHW * kC);
        float r00 = g_rot[s*9+0], r01 = g_rot[s*9+1], r02 = g_rot[s*9+2];
        float r10 = g_rot[s*9+3], r11 = g_rot[s*9+4], r12 = g_rot[s*9+5];
        float r20 = g_rot[s*9+6], r21 = g_rot[s*9+7], r22 = g_rot[s*9+8];
        float trx = g_trans[s*3+0], try_ = g_trans[s*3+1], trz = g_trans[s*3+2];
        float rx = r00*xf + r01*yf + r02;
        float ry = r10*xf + r11*yf + r12;
        float rz = r20*xf + r21*yf + r22;
        float nv0 = g_norv[s*3+0], nv1 = g_norv[s*3+1], nv2 = g_norv[s*3+2];
        float srcw = fmaxf(np0*nv0 + np1*nv1 + np2*nv2, 0.f) + 0.01f;

        float cf[kD];          // cor_feat for my group, all depths
        float s_lane = 0.f;    // logit for d = lane
        unsigned vmask = 0u;   // valid bit per depth (warp-uniform)

#pragma unroll
        for (int d = 0; d < kD; d++) {
            float dep = __shfl_sync(FULL, dep_lane, d);
            float X = rx * dep + trx;
            float Y = ry * dep + try_;
            float Z = rz * dep + trz;
            if (Z == 0.f) Z = 1e-9f;
            float px = X / Z, py = Y / Z;
            // clamp to avoid int overflow; preserves in/out-of-bounds semantics
            px = fminf(fmaxf(px, -4.f), (float)kW + 4.f);
            py = fminf(fmaxf(py, -4.f), (float)kH + 4.f);
            float x0f = floorf(px), y0f = floorf(py);
            float wx = px - x0f, wy = py - y0f;
            int x0 = (int)x0f, y0 = (int)y0f;
            int x1 = x0 + 1, y1 = y0 + 1;
            bool bx0 = (x0 >= 0) && (x0 < kW);
            bool bx1 = (x1 >= 0) && (x1 < kW);
            bool by0 = (y0 >= 0) && (y0 < kH);
            bool by1 = (y1 >= 0) && (y1 < kH);
            float acc = 0.f;
            if (bx0 && by0) acc += (1.f - wx) * (1.f - wy) * srcT[(size_t)(y0*kW + x0)*kC + lane];
            if (bx1 && by0) acc += wx * (1.f - wy)         * srcT[(size_t)(y0*kW + x1)*kC + lane];
            if (bx0 && by1) acc += (1.f - wx) * wy         * srcT[(size_t)(y1*kW + x0)*kC + lane];
            if (bx1 && by1) acc += wx * wy                 * srcT[(size_t)(y1*kW + x1)*kC + lane];
            // valid from channel 0
            float v0 = __shfl_sync(FULL, acc, 0);
            vmask |= (v0 != 0.f) ? (1u << d) : 0u;
            // grouped correlation: mean over 4 channels in my group
            float prod = acc * refc;
            prod += __shfl_xor_sync(FULL, prod, 1);
            prod += __shfl_xor_sync(FULL, prod, 2);
            float cfd = prod * 0.25f;
            cf[d] = cfd;
            // logit = sum over groups of cf
            float tsum = cfd;
            tsum += __shfl_xor_sync(FULL, tsum, 4);
            tsum += __shfl_xor_sync(FULL, tsum, 8);
            tsum += __shfl_xor_sync(FULL, tsum, 16);
            if (lane == d) s_lane = tsum;
        }
        // softmax over depth (lane = depth)
        float m = s_lane;
#pragma unroll
        for (int off = 16; off > 0; off >>= 1)
            m = fmaxf(m, __shfl_xor_sync(FULL, m, off));
        float e = expf(s_lane - m);
        float den = e;
#pragma unroll
        for (int off = 16; off > 0; off >>= 1)
            den += __shfl_xor_sync(FULL, den, off);
        float corw_lane = (e / den) * 0.17677669529663687f;  // / sqrt(C)
        cws_lane += corw_lane;
        float myvalid = (float)((vmask >> lane) & 1u);
        sumw_lane += srcw * myvalid;
        nv_lane += myvalid;
        // accumulate cor_feats
#pragma unroll
        for (int d = 0; d < kD; d++) {
            float cwd = __shfl_sync(FULL, corw_lane, d);
            float swd = srcw * (float)((vmask >> d) & 1u);
            cfacc[d] += cwd * swd * cf[d];
        }
        // sims[s] = mean over D of src_w * valid
        if (lane == 0)
            out[OFF_WT + s * kHW + p] = srcw * (float)__popc(vmask) * (1.f / kD);
    }

    // ---------------- final per-pixel stage ----------------
    float hmin = dec_f(g_min_enc), hmax = dec_f(g_max_enc);
    float nh_lane = (dep_lane - hmin) / (hmax - hmin);

    float logit_lane = 0.f;
#pragma unroll
    for (int d = 0; d < kD; d++) {
        float swd = __shfl_sync(FULL, sumw_lane, d);
        float cwd = __shfl_sync(FULL, cws_lane, d);
        float tsum = wreg_g * (cfacc[d] / swd / cwd);
        tsum += __shfl_xor_sync(FULL, tsum, 1);
        tsum += __shfl_xor_sync(FULL, tsum, 2);
        tsum += __shfl_xor_sync(FULL, tsum, 4);
        tsum += __shfl_xor_sync(FULL, tsum, 8);
        tsum += __shfl_xor_sync(FULL, tsum, 16);
        if (lane == d) logit_lane = tsum * 0.25f + nh_lane;
    }
    // softmax over depth
    float m2 = logit_lane;
#pragma unroll
    for (int off = 16; off > 0; off >>= 1)
        m2 = fmaxf(m2, __shfl_xor_sync(FULL, m2, off));
    float e2 = expf(logit_lane - m2);
    float den2 = e2;
#pragma unroll
    for (int off = 16; off > 0; off >>= 1)
        den2 += __shfl_xor_sync(FULL, den2, off);
    float aw = e2 / den2;
    out[OFF_ATTN + lane * kHW + p] = aw;
    out[OFF_NV + lane * kHW + p] = nv_lane;

    // argmax (first index on tie, matching jnp.argmax)
    float bv = aw; int bi = lane;
#pragma unroll
    for (int off = 16; off > 0; off >>= 1) {
        float ov = __shfl_xor_sync(FULL, bv, off);
        int oi = __shfl_xor_sync(FULL, bi, off);
        if (ov > bv || (ov == bv && oi < bi)) { bv = ov; bi = oi; }
    }
    float depth = __shfl_sync(FULL, dep_lane, bi);
    float d0 = __shfl_sync(FULL, dep_lane, 0);
    float d1 = __shfl_sync(FULL, dep_lane, 1);
    float sw0 = __shfl_sync(FULL, sumw_lane, 0);
    if (lane == 0) {
        out[OFF_DEPTH + p] = depth;
        out[OFF_CONF + p] = bv;
        out[OFF_SW + p] = sw0 * 0.25f;   // / nsrc
        float itv = d1 - d0;
        out[OFF_MIN + p] = depth - itv;
        out[OFF_MAX + p] = depth + itv;
    }
    if (lane < 3) {
        out[OFF_EN + lane * kHW + p] =
            w_norm[lane*3+0]*np0 + w_norm[lane*3+1]*np1 + w_norm[lane*3+2]*np2;
    }
}

// ---------------------------------------------------------------------------
extern "C" void kernel_launch(void* const* d_in, const int* in_sizes, int n_in,
                              void* d_out, int out_size) {
    const float* ref   = (const float*)d_in[0];  // (1,32,192,192)
    const float* src   = (const float*)d_in[1];  // (4,1,32,192,192)
    const float* rotn  = (const float*)d_in[2];  // (1,5,3,3)
    const float* normp = (const float*)d_in[3];  // (1,3,192,192)
    const float* projm = (const float*)d_in[4];  // (1,5,2,4,4)
    const float* dhypo = (const float*)d_in[5];  // (1,32,192,192)
    const float* wreg  = (const float*)d_in[6];  // (8,)
    const float* wnorm = (const float*)d_in[7];  // (3,3)
    float* out = (float*)d_out;

    setup_kernel<<<1, 1>>>(rotn, projm);
    dim3 tb(32, 32);
    dim3 tg(kW / 32, kH, 5);
    transpose_kernel<<<tg, tb>>>(ref, src);
    minmax_kernel<<<256, 256>>>(dhypo);
    main_kernel<<<kHW / 4, 128>>>(normp, dhypo, wreg, wnorm, out);
}

// round 8
// speedup vs baseline: 1.7838x; 1.7838x over previous
#include <cuda_runtime.h>
#include <math.h>

// ---------------------------------------------------------------------------
// Problem constants
// ---------------------------------------------------------------------------
namespace {
constexpr int kC = 32, kG = 8, kD = 32, kH = 192, kW = 192;
constexpr int kHW = kH * kW;
constexpr int kNS = 4;   // nsrc = V-1

// output layout (concatenated tuple, all f32)
constexpr int OFF_DEPTH = 0;
constexpr int OFF_CONF  = OFF_DEPTH + kHW;
constexpr int OFF_ATTN  = OFF_CONF + kHW;            // (D,H,W)
constexpr int OFF_EN    = OFF_ATTN + kD * kHW;       // (3,H,W)
constexpr int OFF_SW    = OFF_EN + 3 * kHW;          // (H,W)
constexpr int OFF_WT    = OFF_SW + kHW;              // (NS,H,W)
constexpr int OFF_NV    = OFF_WT + kNS * kHW;        // (D,H,W)
constexpr int OFF_MIN   = OFF_NV + kD * kHW;         // (H,W)
constexpr int OFF_MAX   = OFF_MIN + kHW;             // (H,W)
}

// ---------------------------------------------------------------------------
// Scratch (static __device__ arrays: no allocation allowed)
// ---------------------------------------------------------------------------
__device__ float g_ref_t[kHW * kC];              // ref features (H,W,C)
__device__ float g_src_t[kNS * kHW * kC];        // src features (ns,H,W,C)
__device__ float g_rot[kNS * 9];
__device__ float g_trans[kNS * 3];
__device__ float g_norv[kNS * 3];
__device__ unsigned g_min_enc, g_max_enc;

// order-preserving float<->uint encoding (for atomic min/max)
__device__ __forceinline__ unsigned enc_f(float x) {
    unsigned u = __float_as_uint(x);
    return (u & 0x80000000u) ? ~u : (u | 0x80000000u);
}
__device__ __forceinline__ float dec_f(unsigned u) {
    return (u & 0x80000000u) ? __uint_as_float(u & 0x7FFFFFFFu)
                             : __uint_as_float(~u);
}

// ---------------------------------------------------------------------------
// Setup: projection matrices, relative rotations, min/max init (1 thread)
// ---------------------------------------------------------------------------
__device__ void inv3(const double* a, double* o) {
    double c00 =   a[4]*a[8] - a[5]*a[7];
    double c01 = -(a[3]*a[8] - a[5]*a[6]);
    double c02 =   a[3]*a[7] - a[4]*a[6];
    double det = a[0]*c00 + a[1]*c01 + a[2]*c02;
    double id = 1.0 / det;
    o[0] =  c00 * id;
    o[1] = -(a[1]*a[8] - a[2]*a[7]) * id;
    o[2] =  (a[1]*a[5] - a[2]*a[4]) * id;
    o[3] =  c01 * id;
    o[4] =  (a[0]*a[8] - a[2]*a[6]) * id;
    o[5] = -(a[0]*a[5] - a[2]*a[3]) * id;
    o[6] =  c02 * id;
    o[7] = -(a[0]*a[7] - a[1]*a[6]) * id;
    o[8] =  (a[0]*a[4] - a[1]*a[3]) * id;
}
__device__ void mm3(const double* a, const double* b, double* o) {
    for (int r = 0; r < 3; r++)
        for (int c = 0; c < 3; c++)
            o[r*3+c] = a[r*3]*b[c] + a[r*3+1]*b[3+c] + a[r*3+2]*b[6+c];
}

__global__ void setup_kernel(const float* __restrict__ rotation,
                             const float* __restrict__ proj) {
    if (threadIdx.x != 0 || blockIdx.x != 0) return;
    g_min_enc = 0xFFFFFFFFu;
    g_max_enc = 0u;
    // proj layout: (1, 5, 2, 4, 4) : [view][E|K][4][4]
    // M_v = K33 @ E33 ; t_v = K33 @ E[:3,3]
    double M[5][9], t[5][3];
    for (int v = 0; v < 5; v++) {
        const float* E = proj + v * 32;
        const float* K = proj + v * 32 + 16;
        for (int r = 0; r < 3; r++) {
            for (int c = 0; c < 3; c++) {
                double s = 0.0;
                for (int k = 0; k < 3; k++) s += (double)K[r*4+k] * (double)E[k*4+c];
                M[v][r*3+c] = s;
            }
            double s = 0.0;
            for (int k = 0; k < 3; k++) s += (double)K[r*4+k] * (double)E[k*4+3];
            t[v][r] = s;
        }
    }
    double MrI[9]; inv3(M[0], MrI);
    double R0[9];  for (int i = 0; i < 9; i++) R0[i] = (double)rotation[i];
    double R0I[9]; inv3(R0, R0I);
    for (int s = 0; s < kNS; s++) {
        int v = s + 1;
        // proj = src_new @ inv(ref_new): rot = Ms Mr^-1, trans = ts - rot tr
        double R[9]; mm3(M[v], MrI, R);
        for (int i = 0; i < 9; i++) g_rot[s*9+i] = (float)R[i];
        for (int r = 0; r < 3; r++) {
            double tr = t[v][r];
            for (int c = 0; c < 3; c++) tr -= R[r*3+c] * t[0][c];
            g_trans[s*3+r] = (float)tr;
        }
        // norv = row 2 of (R_v @ R_0^-1)
        double Rv[9]; for (int i = 0; i < 9; i++) Rv[i] = (double)rotation[v*9+i];
        double Rel[9]; mm3(Rv, R0I, Rel);
        for (int c = 0; c < 3; c++) g_norv[s*3+c] = (float)Rel[6+c];
    }
}

// ---------------------------------------------------------------------------
// Transpose features (C,H,W) -> (H,W,C), 5 views. Coalesced both sides.
// ---------------------------------------------------------------------------
__global__ void transpose_kernel(const float* __restrict__ ref,
                                 const float* __restrict__ src) {
    __shared__ float tile[32][33];
    int v = blockIdx.z;
    const float* in = (v == 0) ? ref : (src + (size_t)(v - 1) * kC * kHW);
    float* out = (v == 0) ? g_ref_t : (g_src_t + (size_t)(v - 1) * kHW * kC);
    int wbase = blockIdx.x * 32;
    int h = blockIdx.y;
    int tx = threadIdx.x, ty = threadIdx.y;   // ty = channel on read
    tile[ty][tx] = in[(size_t)ty * kHW + h * kW + wbase + tx];
    __syncthreads();
    out[(size_t)(h * kW + wbase + ty) * kC + tx] = tile[tx][ty];
}

// ---------------------------------------------------------------------------
// hmin / hmax reduction over depth_hypo
// ---------------------------------------------------------------------------
__global__ void minmax_kernel(const float* __restrict__ dh) {
    __shared__ unsigned smn[256], smx[256];
    unsigned lmn = 0xFFFFFFFFu, lmx = 0u;
    for (int i = blockIdx.x * blockDim.x + threadIdx.x; i < kD * kHW;
         i += gridDim.x * blockDim.x) {
        unsigned e = enc_f(dh[i]);
        lmn = min(lmn, e);
        lmx = max(lmx, e);
    }
    smn[threadIdx.x] = lmn; smx[threadIdx.x] = lmx;
    __syncthreads();
    for (int s = 128; s > 0; s >>= 1) {
        if (threadIdx.x < s) {
            smn[threadIdx.x] = min(smn[threadIdx.x], smn[threadIdx.x + s]);
            smx[threadIdx.x] = max(smx[threadIdx.x], smx[threadIdx.x + s]);
        }
        __syncthreads();
    }
    if (threadIdx.x == 0) {
        atomicMin(&g_min_enc, smn[0]);
        atomicMax(&g_max_enc, smx[0]);
    }
}

// ---------------------------------------------------------------------------
// Main fused kernel: one warp per pixel, lane = channel (C=32), D=32=warpSize
// Fused (max-free) softmax inside the depth loop; valid mask built on lane 0.
// ---------------------------------------------------------------------------
__global__ __launch_bounds__(128, 4) void main_kernel(
    const float* __restrict__ normal_plane,
    const float* __restrict__ depth_hypo,
    const float* __restrict__ w_reg,
    const float* __restrict__ w_norm,
    float* __restrict__ out)
{
    const unsigned FULL = 0xFFFFFFFFu;
    int p = blockIdx.x * 4 + (threadIdx.x >> 5);
    int lane = threadIdx.x & 31;
    float xf = (float)(p % kW), yf = (float)(p / kW);

    float refc = g_ref_t[p * kC + lane];                    // ref feature, my channel
    float np0 = normal_plane[p];
    float np1 = normal_plane[kHW + p];
    float np2 = normal_plane[2 * kHW + p];
    float wreg_g = w_reg[lane >> 2];
    float dep_lane = depth_hypo[lane * kHW + p];            // lane l holds depth l

    float cfacc[kD];                                        // cor_feats[g(lane), d]
#pragma unroll
    for (int d = 0; d < kD; d++) cfacc[d] = 0.f;
    float cws_lane  = 1e-8f;   // cor_weight_sum[d=lane]
    float sumw_lane = 1e-8f;   // sum_weight[d=lane]
    float nv_lane   = 0.f;     // num_valid[d=lane]

#pragma unroll 1
    for (int s = 0; s < kNS; s++) {
        const float* srcL = g_src_t + s * (kHW * kC) + lane;
        float r00 = g_rot[s*9+0], r01 = g_rot[s*9+1], r02 = g_rot[s*9+2];
        float r10 = g_rot[s*9+3], r11 = g_rot[s*9+4], r12 = g_rot[s*9+5];
        float r20 = g_rot[s*9+6], r21 = g_rot[s*9+7], r22 = g_rot[s*9+8];
        float trx = g_trans[s*3+0], try_ = g_trans[s*3+1], trz = g_trans[s*3+2];
        float rx = r00*xf + r01*yf + r02;
        float ry = r10*xf + r11*yf + r12;
        float rz = r20*xf + r21*yf + r22;
        float nv0 = g_norv[s*3+0], nv1 = g_norv[s*3+1], nv2 = g_norv[s*3+2];
        float srcw = fmaxf(np0*nv0 + np1*nv1 + np2*nv2, 0.f) + 0.01f;

        float t[kD];           // e_d * cf_d (group value), scaled at source end
        float den = 0.f;       // softmax denominator (max-free; logits are O(10))
        float my_e = 0.f;      // e_d at d == lane
        unsigned vmask = 0u;   // valid bits, built on lane 0 only

#pragma unroll
        for (int d = 0; d < kD; d++) {
            float dep = __shfl_sync(FULL, dep_lane, d);
            float X = fmaf(rx, dep, trx);
            float Y = fmaf(ry, dep, try_);
            float Z = fmaf(rz, dep, trz);
            if (Z == 0.f) Z = 1e-9f;
            float rZ = __fdividef(1.f, Z);
            float px = X * rZ, py = Y * rZ;
            // clamp to avoid int overflow; preserves in/out-of-bounds semantics
            px = fminf(fmaxf(px, -4.f), (float)kW + 4.f);
            py = fminf(fmaxf(py, -4.f), (float)kH + 4.f);
            float x0f = floorf(px), y0f = floorf(py);
            float wx = px - x0f, wy = py - y0f;
            int x0 = (int)x0f, y0 = (int)y0f;
            bool bx0 = (unsigned)x0 < (unsigned)kW;
            bool bx1 = (unsigned)(x0 + 1) < (unsigned)kW;
            bool by0 = (unsigned)y0 < (unsigned)kH;
            bool by1 = (unsigned)(y0 + 1) < (unsigned)kH;
            int base = y0 * (kW * kC) + x0 * kC;
            float owx = 1.f - wx, owy = 1.f - wy;
            float acc = 0.f;
            if (bx0 && by0) acc = fmaf(owx * owy, srcL[base], acc);
            if (bx1 && by0) acc = fmaf(wx  * owy, srcL[base + kC], acc);
            if (bx0 && by1) acc = fmaf(owx * wy,  srcL[base + kW*kC], acc);
            if (bx1 && by1) acc = fmaf(wx  * wy,  srcL[base + kW*kC + kC], acc);
            if (lane == 0) vmask |= (acc != 0.f) ? (1u << d) : 0u;
            // grouped correlation: mean over 4 channels in my group
            float prod = acc * refc;
            prod += __shfl_xor_sync(FULL, prod, 1);
            prod += __shfl_xor_sync(FULL, prod, 2);
            float cfd = prod * 0.25f;
            // logit = sum over groups of cfd (butterfly broadcasts to all lanes)
            float tsum = cfd;
            tsum += __shfl_xor_sync(FULL, tsum, 4);
            tsum += __shfl_xor_sync(FULL, tsum, 8);
            tsum += __shfl_xor_sync(FULL, tsum, 16);
            float e = __expf(tsum);     // logits O(+-10): no max-subtract needed
            den += e;
            if (lane == d) my_e = e;
            t[d] = e * cfd;
        }
        vmask = __shfl_sync(FULL, vmask, 0);

        float factor = __fdividef(0.17677669529663687f, den);  // (1/sqrt(C)) / den
        cws_lane += my_e * factor;
        float mybit = (float)((vmask >> lane) & 1u);
        sumw_lane += srcw * mybit;
        nv_lane += mybit;
#pragma unroll
        for (int d = 0; d < kD; d++) {
            float swd = ((vmask >> d) & 1u) ? srcw : 0.f;
            cfacc[d] = fmaf(t[d], swd * factor, cfacc[d]);
        }
        // sims[s] = mean over D of src_w * valid
        if (lane == 0)
            out[OFF_WT + s * kHW + p] = srcw * (float)__popc(vmask) * (1.f / kD);
    }

    // ---------------- final per-pixel stage ----------------
    float hmin = dec_f(g_min_enc), hmax = dec_f(g_max_enc);
    float nh_lane = (dep_lane - hmin) / (hmax - hmin);

    float sel = 0.f;
#pragma unroll
    for (int d = 0; d < kD; d++) {
        float v = wreg_g * cfacc[d];
        v += __shfl_xor_sync(FULL, v, 1);
        v += __shfl_xor_sync(FULL, v, 2);
        v += __shfl_xor_sync(FULL, v, 4);
        v += __shfl_xor_sync(FULL, v, 8);
        v += __shfl_xor_sync(FULL, v, 16);
        if (lane == d) sel = v;   // sel = 4 * sum_g wreg_g * cfacc_g[d]
    }
    float logit_lane =
        sel * 0.25f * __fdividef(1.f, sumw_lane * cws_lane) + nh_lane;

    // softmax over depth (keep max for robustness; cheap)
    float m2 = logit_lane;
#pragma unroll
    for (int off = 16; off > 0; off >>= 1)
        m2 = fmaxf(m2, __shfl_xor_sync(FULL, m2, off));
    float e2 = __expf(logit_lane - m2);
    float den2 = e2;
#pragma unroll
    for (int off = 16; off > 0; off >>= 1)
        den2 += __shfl_xor_sync(FULL, den2, off);
    float aw = e2 / den2;
    out[OFF_ATTN + lane * kHW + p] = aw;
    out[OFF_NV + lane * kHW + p] = nv_lane;

    // argmax (first index on tie, matching jnp.argmax)
    float bv = aw; int bi = lane;
#pragma unroll
    for (int off = 16; off > 0; off >>= 1) {
        float ov = __shfl_xor_sync(FULL, bv, off);
        int oi = __shfl_xor_sync(FULL, bi, off);
        if (ov > bv || (ov == bv && oi < bi)) { bv = ov; bi = oi; }
    }
    float depth = __shfl_sync(FULL, dep_lane, bi);
    float d0 = __shfl_sync(FULL, dep_lane, 0);
    float d1 = __shfl_sync(FULL, dep_lane, 1);
    float sw0 = __shfl_sync(FULL, sumw_lane, 0);
    if (lane == 0) {
        out[OFF_DEPTH + p] = depth;
        out[OFF_CONF + p] = bv;
        out[OFF_SW + p] = sw0 * 0.25f;   // / nsrc
        float itv = d1 - d0;
        out[OFF_MIN + p] = depth - itv;
        out[OFF_MAX + p] = depth + itv;
    }
    if (lane < 3) {
        out[OFF_EN + lane * kHW + p] =
            w_norm[lane*3+0]*np0 + w_norm[lane*3+1]*np1 + w_norm[lane*3+2]*np2;
    }
}

// ---------------------------------------------------------------------------
extern "C" void kernel_launch(void* const* d_in, const int* in_sizes, int n_in,
                              void* d_out, int out_size) {
    const float* ref   = (const float*)d_in[0];  // (1,32,192,192)
    const float* src   = (const float*)d_in[1];  // (4,1,32,192,192)
    const float* rotn  = (const float*)d_in[2];  // (1,5,3,3)
    const float* normp = (const float*)d_in[3];  // (1,3,192,192)
    const float* projm = (const float*)d_in[4];  // (1,5,2,4,4)
    const float* dhypo = (const float*)d_in[5];  // (1,32,192,192)
    const float* wreg  = (const float*)d_in[6];  // (8,)
    const float* wnorm = (const float*)d_in[7];  // (3,3)
    float* out = (float*)d_out;

    setup_kernel<<<1, 1>>>(rotn, projm);
    dim3 tb(32, 32);
    dim3 tg(kW / 32, kH, 5);
    transpose_kernel<<<tg, tb>>>(ref, src);
    minmax_kernel<<<256, 256>>>(dhypo);
    main_kernel<<<kHW / 4, 128>>>(normp, dhypo, wreg, wnorm, out);
}

// round 9
// speedup vs baseline: 1.8311x; 1.0265x over previous
#include <cuda_runtime.h>
#include <math.h>

// ---------------------------------------------------------------------------
// Problem constants
// ---------------------------------------------------------------------------
namespace {
constexpr int kC = 32, kG = 8, kD = 32, kH = 192, kW = 192;
constexpr int kHW = kH * kW;
constexpr int kNS = 4;   // nsrc = V-1

// output layout (concatenated tuple, all f32)
constexpr int OFF_DEPTH = 0;
constexpr int OFF_CONF  = OFF_DEPTH + kHW;
constexpr int OFF_ATTN  = OFF_CONF + kHW;            // (D,H,W)
constexpr int OFF_EN    = OFF_ATTN + kD * kHW;       // (3,H,W)
constexpr int OFF_SW    = OFF_EN + 3 * kHW;          // (H,W)
constexpr int OFF_WT    = OFF_SW + kHW;              // (NS,H,W)
constexpr int OFF_NV    = OFF_WT + kNS * kHW;        // (D,H,W)
constexpr int OFF_MIN   = OFF_NV + kD * kHW;         // (H,W)
constexpr int OFF_MAX   = OFF_MIN + kHW;             // (H,W)
}

// ---------------------------------------------------------------------------
// Scratch (static __device__ arrays: no allocation allowed)
// ---------------------------------------------------------------------------
__device__ float g_ref_t[kHW * kC];              // ref features (H,W,C)
__device__ float g_src_t[kNS * kHW * kC];        // src features (ns,H,W,C)
__device__ float g_rot[kNS * 9];
__device__ float g_trans[kNS * 3];
__device__ float g_norv[kNS * 3];
__device__ unsigned g_min_enc, g_max_enc;

// order-preserving float<->uint encoding (for atomic min/max)
__device__ __forceinline__ unsigned enc_f(float x) {
    unsigned u = __float_as_uint(x);
    return (u & 0x80000000u) ? ~u : (u | 0x80000000u);
}
__device__ __forceinline__ float dec_f(unsigned u) {
    return (u & 0x80000000u) ? __uint_as_float(u & 0x7FFFFFFFu)
                             : __uint_as_float(~u);
}

// ---------------------------------------------------------------------------
// Setup: projection matrices, relative rotations, min/max init (1 thread)
// ---------------------------------------------------------------------------
__device__ void inv3(const double* a, double* o) {
    double c00 =   a[4]*a[8] - a[5]*a[7];
    double c01 = -(a[3]*a[8] - a[5]*a[6]);
    double c02 =   a[3]*a[7] - a[4]*a[6];
    double det = a[0]*c00 + a[1]*c01 + a[2]*c02;
    double id = 1.0 / det;
    o[0] =  c00 * id;
    o[1] = -(a[1]*a[8] - a[2]*a[7]) * id;
    o[2] =  (a[1]*a[5] - a[2]*a[4]) * id;
    o[3] =  c01 * id;
    o[4] =  (a[0]*a[8] - a[2]*a[6]) * id;
    o[5] = -(a[0]*a[5] - a[2]*a[3]) * id;
    o[6] =  c02 * id;
    o[7] = -(a[0]*a[7] - a[1]*a[6]) * id;
    o[8] =  (a[0]*a[4] - a[1]*a[3]) * id;
}
__device__ void mm3(const double* a, const double* b, double* o) {
    for (int r = 0; r < 3; r++)
        for (int c = 0; c < 3; c++)
            o[r*3+c] = a[r*3]*b[c] + a[r*3+1]*b[3+c] + a[r*3+2]*b[6+c];
}

__global__ void setup_kernel(const float* __restrict__ rotation,
                             const float* __restrict__ proj) {
    if (threadIdx.x != 0 || blockIdx.x != 0) return;
    g_min_enc = 0xFFFFFFFFu;
    g_max_enc = 0u;
    // proj layout: (1, 5, 2, 4, 4) : [view][E|K][4][4]
    // M_v = K33 @ E33 ; t_v = K33 @ E[:3,3]
    double M[5][9], t[5][3];
    for (int v = 0; v < 5; v++) {
        const float* E = proj + v * 32;
        const float* K = proj + v * 32 + 16;
        for (int r = 0; r < 3; r++) {
            for (int c = 0; c < 3; c++) {
                double s = 0.0;
                for (int k = 0; k < 3; k++) s += (double)K[r*4+k] * (double)E[k*4+c];
                M[v][r*3+c] = s;
            }
            double s = 0.0;
            for (int k = 0; k < 3; k++) s += (double)K[r*4+k] * (double)E[k*4+3];
            t[v][r] = s;
        }
    }
    double MrI[9]; inv3(M[0], MrI);
    double R0[9];  for (int i = 0; i < 9; i++) R0[i] = (double)rotation[i];
    double R0I[9]; inv3(R0, R0I);
    for (int s = 0; s < kNS; s++) {
        int v = s + 1;
        // proj = src_new @ inv(ref_new): rot = Ms Mr^-1, trans = ts - rot tr
        double R[9]; mm3(M[v], MrI, R);
        for (int i = 0; i < 9; i++) g_rot[s*9+i] = (float)R[i];
        for (int r = 0; r < 3; r++) {
            double tr = t[v][r];
            for (int c = 0; c < 3; c++) tr -= R[r*3+c] * t[0][c];
            g_trans[s*3+r] = (float)tr;
        }
        // norv = row 2 of (R_v @ R_0^-1)
        double Rv[9]; for (int i = 0; i < 9; i++) Rv[i] = (double)rotation[v*9+i];
        double Rel[9]; mm3(Rv, R0I, Rel);
        for (int c = 0; c < 3; c++) g_norv[s*3+c] = (float)Rel[6+c];
    }
}

// ---------------------------------------------------------------------------
// Transpose features (C,H,W) -> (H,W,C), 5 views. Coalesced both sides.
// ---------------------------------------------------------------------------
__global__ void transpose_kernel(const float* __restrict__ ref,
                                 const float* __restrict__ src) {
    __shared__ float tile[32][33];
    int v = blockIdx.z;
    const float* in = (v == 0) ? ref : (src + (size_t)(v - 1) * kC * kHW);
    float* out = (v == 0) ? g_ref_t : (g_src_t + (size_t)(v - 1) * kHW * kC);
    int wbase = blockIdx.x * 32;
    int h = blockIdx.y;
    int tx = threadIdx.x, ty = threadIdx.y;   // ty = channel on read
    tile[ty][tx] = in[(size_t)ty * kHW + h * kW + wbase + tx];
    __syncthreads();
    out[(size_t)(h * kW + wbase + ty) * kC + tx] = tile[tx][ty];
}

// ---------------------------------------------------------------------------
// hmin / hmax reduction over depth_hypo
// ---------------------------------------------------------------------------
__global__ void minmax_kernel(const float* __restrict__ dh) {
    __shared__ unsigned smn[256], smx[256];
    unsigned lmn = 0xFFFFFFFFu, lmx = 0u;
    for (int i = blockIdx.x * blockDim.x + threadIdx.x; i < kD * kHW;
         i += gridDim.x * blockDim.x) {
        unsigned e = enc_f(dh[i]);
        lmn = min(lmn, e);
        lmx = max(lmx, e);
    }
    smn[threadIdx.x] = lmn; smx[threadIdx.x] = lmx;
    __syncthreads();
    for (int s = 128; s > 0; s >>= 1) {
        if (threadIdx.x < s) {
            smn[threadIdx.x] = min(smn[threadIdx.x], smn[threadIdx.x + s]);
            smx[threadIdx.x] = max(smx[threadIdx.x], smx[threadIdx.x + s]);
        }
        __syncthreads();
    }
    if (threadIdx.x == 0) {
        atomicMin(&g_min_enc, smn[0]);
        atomicMax(&g_max_enc, smx[0]);
    }
}

// ---------------------------------------------------------------------------
// Main fused kernel: one warp per pixel, lane = channel (C=32), D=32=warpSize
//
// Key identity: cor_feats is never output; only
//   logit_d = [ Sum_s factor_s * e_sd * swd_s * (Sum_g wreg_g * cfd_sdg) ]
//             / (sumw_d * cws_d) + norm_hypo_d
// so the wreg-weighted group sum (q) is folded into the depth loop and the
// 32-deep register arrays disappear -> ~2x occupancy.
// ---------------------------------------------------------------------------
__global__ __launch_bounds__(128, 8) void main_kernel(
    const float* __restrict__ normal_plane,
    const float* __restrict__ depth_hypo,
    const float* __restrict__ w_reg,
    const float* __restrict__ w_norm,
    float* __restrict__ out)
{
    const unsigned FULL = 0xFFFFFFFFu;
    int p = blockIdx.x * 4 + (threadIdx.x >> 5);
    int lane = threadIdx.x & 31;
    float xf = (float)(p % kW), yf = (float)(p / kW);

    float refc = g_ref_t[p * kC + lane];                    // ref feature, my channel
    float np0 = normal_plane[p];
    float np1 = normal_plane[kHW + p];
    float np2 = normal_plane[2 * kHW + p];
    float wreg_g = w_reg[lane >> 2];
    float dep_lane = depth_hypo[lane * kHW + p];            // lane l holds depth l

    float Lacc      = 0.f;     // numerator of attn logit, d = lane
    float cws_lane  = 1e-8f;   // cor_weight_sum[d=lane]
    float sumw_lane = 1e-8f;   // sum_weight[d=lane]
    float nv_lane   = 0.f;     // num_valid[d=lane]

#pragma unroll 1
    for (int s = 0; s < kNS; s++) {
        const float* srcL = g_src_t + s * (kHW * kC) + lane;
        float r00 = g_rot[s*9+0], r01 = g_rot[s*9+1], r02 = g_rot[s*9+2];
        float r10 = g_rot[s*9+3], r11 = g_rot[s*9+4], r12 = g_rot[s*9+5];
        float r20 = g_rot[s*9+6], r21 = g_rot[s*9+7], r22 = g_rot[s*9+8];
        float trx = g_trans[s*3+0], try_ = g_trans[s*3+1], trz = g_trans[s*3+2];
        float rx = r00*xf + r01*yf + r02;
        float ry = r10*xf + r11*yf + r12;
        float rz = r20*xf + r21*yf + r22;
        float nv0 = g_norv[s*3+0], nv1 = g_norv[s*3+1], nv2 = g_norv[s*3+2];
        float srcw = fmaxf(np0*nv0 + np1*nv1 + np2*nv2, 0.f) + 0.01f;

        float den = 0.f;       // per-src softmax denominator (max-free; logits O(10))
        float my_e = 0.f;      // e_d at d == lane
        float P = 0.f;         // valid_d * e_d * q_d at d == lane
        unsigned vmask = 0u;   // valid bits (all lanes, built from broadcast)

#pragma unroll
        for (int d = 0; d < kD; d++) {
            float dep = __shfl_sync(FULL, dep_lane, d);
            float X = fmaf(rx, dep, trx);
            float Y = fmaf(ry, dep, try_);
            float Z = fmaf(rz, dep, trz);
            if (Z == 0.f) Z = 1e-9f;
            float rZ = __fdividef(1.f, Z);
            float px = X * rZ, py = Y * rZ;
            // clamp to avoid int overflow; preserves in/out-of-bounds semantics
            px = fminf(fmaxf(px, -4.f), (float)kW + 4.f);
            py = fminf(fmaxf(py, -4.f), (float)kH + 4.f);
            float x0f = floorf(px), y0f = floorf(py);
            float wx = px - x0f, wy = py - y0f;
            int x0 = (int)x0f, y0 = (int)y0f;
            bool bx0 = (unsigned)x0 < (unsigned)kW;
            bool bx1 = (unsigned)(x0 + 1) < (unsigned)kW;
            bool by0 = (unsigned)y0 < (unsigned)kH;
            bool by1 = (unsigned)(y0 + 1) < (unsigned)kH;
            int base = y0 * (kW * kC) + x0 * kC;
            float owx = 1.f - wx, owy = 1.f - wy;
            float acc = 0.f;
            if (bx0 && by0) acc = fmaf(owx * owy, srcL[base], acc);
            if (bx1 && by0) acc = fmaf(wx  * owy, srcL[base + kC], acc);
            if (bx0 && by1) acc = fmaf(owx * wy,  srcL[base + kW*kC], acc);
            if (bx1 && by1) acc = fmaf(wx  * wy,  srcL[base + kW*kC + kC], acc);
            // valid flag from channel 0, broadcast to all lanes
            float v0 = __shfl_sync(FULL, acc, 0);
            bool valid = (v0 != 0.f);
            vmask |= valid ? (1u << d) : 0u;
            // grouped correlation: mean over 4 channels in my group
            float prod = acc * refc;
            prod += __shfl_xor_sync(FULL, prod, 1);
            prod += __shfl_xor_sync(FULL, prod, 2);
            float cfd = prod * 0.25f;
            // two group butterflies: ts = Sum_g cfd (softmax logit),
            //                        qv = Sum_g wreg_g*cfd (attn numerator)
            float ts = cfd;
            float qv = cfd * wreg_g;
            ts += __shfl_xor_sync(FULL, ts, 4);
            qv += __shfl_xor_sync(FULL, qv, 4);
            ts += __shfl_xor_sync(FULL, ts, 8);
            qv += __shfl_xor_sync(FULL, qv, 8);
            ts += __shfl_xor_sync(FULL, ts, 16);
            qv += __shfl_xor_sync(FULL, qv, 16);
            float e = __expf(ts);     // logits O(+-10): no max-subtract needed
            den += e;
            if (lane == d) {
                my_e = e;
                P = valid ? e * qv : 0.f;
            }
        }

        float factor = __fdividef(0.17677669529663687f, den);  // (1/sqrt(C)) / den
        cws_lane += my_e * factor;
        float mybit = (float)((vmask >> lane) & 1u);
        sumw_lane += srcw * mybit;
        nv_lane += mybit;
        Lacc = fmaf(P, factor * srcw, Lacc);
        // sims[s] = mean over D of src_w * valid
        if (lane == 0)
            out[OFF_WT + s * kHW + p] = srcw * (float)__popc(vmask) * (1.f / kD);
    }

    // ---------------- final per-pixel stage ----------------
    float hmin = dec_f(g_min_enc), hmax = dec_f(g_max_enc);
    float nh_lane = (dep_lane - hmin) / (hmax - hmin);

    // qv butterfly summed over 32 lanes = 4x the 8-group sum -> *0.25
    float logit_lane =
        Lacc * 0.25f * __fdividef(1.f, sumw_lane * cws_lane) + nh_lane;

    // softmax over depth (keep max for robustness; cheap)
    float m2 = logit_lane;
#pragma unroll
    for (int off = 16; off > 0; off >>= 1)
        m2 = fmaxf(m2, __shfl_xor_sync(FULL, m2, off));
    float e2 = __expf(logit_lane - m2);
    float den2 = e2;
#pragma unroll
    for (int off = 16; off > 0; off >>= 1)
        den2 += __shfl_xor_sync(FULL, den2, off);
    float aw = e2 / den2;
    out[OFF_ATTN + lane * kHW + p] = aw;
    out[OFF_NV + lane * kHW + p] = nv_lane;

    // argmax (first index on tie, matching jnp.argmax)
    float bv = aw; int bi = lane;
#pragma unroll
    for (int off = 16; off > 0; off >>= 1) {
        float ov = __shfl_xor_sync(FULL, bv, off);
        int oi = __shfl_xor_sync(FULL, bi, off);
        if (ov > bv || (ov == bv && oi < bi)) { bv = ov; bi = oi; }
    }
    float depth = __shfl_sync(FULL, dep_lane, bi);
    float d0 = __shfl_sync(FULL, dep_lane, 0);
    float d1 = __shfl_sync(FULL, dep_lane, 1);
    float sw0 = __shfl_sync(FULL, sumw_lane, 0);
    if (lane == 0) {
        out[OFF_DEPTH + p] = depth;
        out[OFF_CONF + p] = bv;
        out[OFF_SW + p] = sw0 * 0.25f;   // / nsrc
        float itv = d1 - d0;
        out[OFF_MIN + p] = depth - itv;
        out[OFF_MAX + p] = depth + itv;
    }
    if (lane < 3) {
        out[OFF_EN + lane * kHW + p] =
            w_norm[lane*3+0]*np0 + w_norm[lane*3+1]*np1 + w_norm[lane*3+2]*np2;
    }
}

// ---------------------------------------------------------------------------
extern "C" void kernel_launch(void* const* d_in, const int* in_sizes, int n_in,
                              void* d_out, int out_size) {
    const float* ref   = (const float*)d_in[0];  // (1,32,192,192)
    const float* src   = (const float*)d_in[1];  // (4,1,32,192,192)
    const float* rotn  = (const float*)d_in[2];  // (1,5,3,3)
    const float* normp = (const float*)d_in[3];  // (1,3,192,192)
    const float* projm = (const float*)d_in[4];  // (1,5,2,4,4)
    const float* dhypo = (const float*)d_in[5];  // (1,32,192,192)
    const float* wreg  = (const float*)d_in[6];  // (8,)
    const float* wnorm = (const float*)d_in[7];  // (3,3)
    float* out = (float*)d_out;

    setup_kernel<<<1, 1>>>(rotn, projm);
    dim3 tb(32, 32);
    dim3 tg(kW / 32, kH, 5);
    transpose_kernel<<<tg, tb>>>(ref, src);
    minmax_kernel<<<256, 256>>>(dhypo);
    main_kernel<<<kHW / 4, 128>>>(normp, dhypo, wreg, wnorm, out);
}

// round 10
// speedup vs baseline: 1.8471x; 1.0087x over previous
#include <cuda_runtime.h>
#include <math.h>

// ---------------------------------------------------------------------------
// Problem constants
// ---------------------------------------------------------------------------
namespace {
constexpr int kC = 32, kG = 8, kD = 32, kH = 192, kW = 192;
constexpr int kHW = kH * kW;
constexpr int kNS = 4;   // nsrc = V-1

// output layout (concatenated tuple, all f32)
constexpr int OFF_DEPTH = 0;
constexpr int OFF_CONF  = OFF_DEPTH + kHW;
constexpr int OFF_ATTN  = OFF_CONF + kHW;            // (D,H,W)
constexpr int OFF_EN    = OFF_ATTN + kD * kHW;       // (3,H,W)
constexpr int OFF_SW    = OFF_EN + 3 * kHW;          // (H,W)
constexpr int OFF_WT    = OFF_SW + kHW;              // (NS,H,W)
constexpr int OFF_NV    = OFF_WT + kNS * kHW;        // (D,H,W)
constexpr int OFF_MIN   = OFF_NV + kD * kHW;         // (H,W)
constexpr int OFF_MAX   = OFF_MIN + kHW;             // (H,W)
}

// ---------------------------------------------------------------------------
// Scratch (static __device__ arrays: no allocation allowed)
// ---------------------------------------------------------------------------
__device__ float g_ref_t[kHW * kC];              // ref features (H,W,C)
__device__ float g_src_t[kNS * kHW * kC];        // src features (ns,H,W,C)
__device__ float g_rot[kNS * 9];
__device__ float g_trans[kNS * 3];
__device__ float g_norv[kNS * 3];
__device__ unsigned g_min_enc, g_max_enc;

// order-preserving float<->uint encoding (for atomic min/max)
__device__ __forceinline__ unsigned enc_f(float x) {
    unsigned u = __float_as_uint(x);
    return (u & 0x80000000u) ? ~u : (u | 0x80000000u);
}
__device__ __forceinline__ float dec_f(unsigned u) {
    return (u & 0x80000000u) ? __uint_as_float(u & 0x7FFFFFFFu)
                             : __uint_as_float(~u);
}

// ---------------------------------------------------------------------------
// Setup: projection matrices, relative rotations, min/max init (1 thread)
// ---------------------------------------------------------------------------
__device__ void inv3(const double* a, double* o) {
    double c00 =   a[4]*a[8] - a[5]*a[7];
    double c01 = -(a[3]*a[8] - a[5]*a[6]);
    double c02 =   a[3]*a[7] - a[4]*a[6];
    double det = a[0]*c00 + a[1]*c01 + a[2]*c02;
    double id = 1.0 / det;
    o[0] =  c00 * id;
    o[1] = -(a[1]*a[8] - a[2]*a[7]) * id;
    o[2] =  (a[1]*a[5] - a[2]*a[4]) * id;
    o[3] =  c01 * id;
    o[4] =  (a[0]*a[8] - a[2]*a[6]) * id;
    o[5] = -(a[0]*a[5] - a[2]*a[3]) * id;
    o[6] =  c02 * id;
    o[7] = -(a[0]*a[7] - a[1]*a[6]) * id;
    o[8] =  (a[0]*a[4] - a[1]*a[3]) * id;
}
__device__ void mm3(const double* a, const double* b, double* o) {
    for (int r = 0; r < 3; r++)
        for (int c = 0; c < 3; c++)
            o[r*3+c] = a[r*3]*b[c] + a[r*3+1]*b[3+c] + a[r*3+2]*b[6+c];
}

__global__ void setup_kernel(const float* __restrict__ rotation,
                             const float* __restrict__ proj) {
    if (threadIdx.x != 0 || blockIdx.x != 0) return;
    g_min_enc = 0xFFFFFFFFu;
    g_max_enc = 0u;
    // proj layout: (1, 5, 2, 4, 4) : [view][E|K][4][4]
    // M_v = K33 @ E33 ; t_v = K33 @ E[:3,3]
    double M[5][9], t[5][3];
    for (int v = 0; v < 5; v++) {
        const float* E = proj + v * 32;
        const float* K = proj + v * 32 + 16;
        for (int r = 0; r < 3; r++) {
            for (int c = 0; c < 3; c++) {
                double s = 0.0;
                for (int k = 0; k < 3; k++) s += (double)K[r*4+k] * (double)E[k*4+c];
                M[v][r*3+c] = s;
            }
            double s = 0.0;
            for (int k = 0; k < 3; k++) s += (double)K[r*4+k] * (double)E[k*4+3];
            t[v][r] = s;
        }
    }
    double MrI[9]; inv3(M[0], MrI);
    double R0[9];  for (int i = 0; i < 9; i++) R0[i] = (double)rotation[i];
    double R0I[9]; inv3(R0, R0I);
    for (int s = 0; s < kNS; s++) {
        int v = s + 1;
        // proj = src_new @ inv(ref_new): rot = Ms Mr^-1, trans = ts - rot tr
        double R[9]; mm3(M[v], MrI, R);
        for (int i = 0; i < 9; i++) g_rot[s*9+i] = (float)R[i];
        for (int r = 0; r < 3; r++) {
            double tr = t[v][r];
            for (int c = 0; c < 3; c++) tr -= R[r*3+c] * t[0][c];
            g_trans[s*3+r] = (float)tr;
        }
        // norv = row 2 of (R_v @ R_0^-1)
        double Rv[9]; for (int i = 0; i < 9; i++) Rv[i] = (double)rotation[v*9+i];
        double Rel[9]; mm3(Rv, R0I, Rel);
        for (int c = 0; c < 3; c++) g_norv[s*3+c] = (float)Rel[6+c];
    }
}

// ---------------------------------------------------------------------------
// Transpose features (C,H,W) -> (H,W,C), 5 views. Coalesced both sides.
// ---------------------------------------------------------------------------
__global__ void transpose_kernel(const float* __restrict__ ref,
                                 const float* __restrict__ src) {
    __shared__ float tile[32][33];
    int v = blockIdx.z;
    const float* in = (v == 0) ? ref : (src + (size_t)(v - 1) * kC * kHW);
    float* out = (v == 0) ? g_ref_t : (g_src_t + (size_t)(v - 1) * kHW * kC);
    int wbase = blockIdx.x * 32;
    int h = blockIdx.y;
    int tx = threadIdx.x, ty = threadIdx.y;   // ty = channel on read
    tile[ty][tx] = in[(size_t)ty * kHW + h * kW + wbase + tx];
    __syncthreads();
    out[(size_t)(h * kW + wbase + ty) * kC + tx] = tile[tx][ty];
}

// ---------------------------------------------------------------------------
// hmin / hmax reduction over depth_hypo
// ---------------------------------------------------------------------------
__global__ void minmax_kernel(const float* __restrict__ dh) {
    __shared__ unsigned smn[256], smx[256];
    unsigned lmn = 0xFFFFFFFFu, lmx = 0u;
    for (int i = blockIdx.x * blockDim.x + threadIdx.x; i < kD * kHW;
         i += gridDim.x * blockDim.x) {
        unsigned e = enc_f(dh[i]);
        lmn = min(lmn, e);
        lmx = max(lmx, e);
    }
    smn[threadIdx.x] = lmn; smx[threadIdx.x] = lmx;
    __syncthreads();
    for (int s = 128; s > 0; s >>= 1) {
        if (threadIdx.x < s) {
            smn[threadIdx.x] = min(smn[threadIdx.x], smn[threadIdx.x + s]);
            smx[threadIdx.x] = max(smx[threadIdx.x], smx[threadIdx.x + s]);
        }
        __syncthreads();
    }
    if (threadIdx.x == 0) {
        atomicMin(&g_min_enc, smn[0]);
        atomicMax(&g_max_enc, smx[0]);
    }
}

// ---------------------------------------------------------------------------
// Main fused kernel: one warp per pixel, lane = channel (C=32), D=32=warpSize
//
// cor_feats is never output; only
//   logit_d = [ Sum_s factor_s * e_sd * swd_s * (Sum_g wreg_g * cfd_sdg) ]
//             / (sumw_d * cws_d) + norm_hypo_d
// Valid mask is built on lane 0 and applied AFTER the depth loop (mybit),
// removing the per-iteration validity broadcast.
// ---------------------------------------------------------------------------
__global__ __launch_bounds__(128, 8) void main_kernel(
    const float* __restrict__ normal_plane,
    const float* __restrict__ depth_hypo,
    const float* __restrict__ w_reg,
    const float* __restrict__ w_norm,
    float* __restrict__ out)
{
    const unsigned FULL = 0xFFFFFFFFu;
    int p = blockIdx.x * 4 + (threadIdx.x >> 5);
    int lane = threadIdx.x & 31;
    float xf = (float)(p % kW), yf = (float)(p / kW);

    float refc4 = g_ref_t[p * kC + lane] * 0.25f;  // ref feature * 1/4 (group mean prefold)
    float np0 = normal_plane[p];
    float np1 = normal_plane[kHW + p];
    float np2 = normal_plane[2 * kHW + p];
    float wreg_g = w_reg[lane >> 2];
    float dep_lane = depth_hypo[lane * kHW + p];   // lane l holds depth l

    float Lacc      = 0.f;     // numerator of attn logit, d = lane
    float cws_lane  = 1e-8f;   // cor_weight_sum[d=lane]
    float sumw_lane = 1e-8f;   // sum_weight[d=lane]
    float nv_lane   = 0.f;     // num_valid[d=lane]

#pragma unroll 1
    for (int s = 0; s < kNS; s++) {
        const float* srcL = g_src_t + s * (kHW * kC) + lane;
        float r00 = g_rot[s*9+0], r01 = g_rot[s*9+1], r02 = g_rot[s*9+2];
        float r10 = g_rot[s*9+3], r11 = g_rot[s*9+4], r12 = g_rot[s*9+5];
        float r20 = g_rot[s*9+6], r21 = g_rot[s*9+7], r22 = g_rot[s*9+8];
        float trx = g_trans[s*3+0], try_ = g_trans[s*3+1], trz = g_trans[s*3+2];
        float rx = r00*xf + r01*yf + r02;
        float ry = r10*xf + r11*yf + r12;
        float rz = r20*xf + r21*yf + r22;
        float nv0 = g_norv[s*3+0], nv1 = g_norv[s*3+1], nv2 = g_norv[s*3+2];
        float srcw = fmaxf(np0*nv0 + np1*nv1 + np2*nv2, 0.f) + 0.01f;

        float den = 0.f;       // per-src softmax denominator (max-free; logits O(10))
        float my_e = 0.f;      // e_d at d == lane
        float P = 0.f;         // e_d * q_d at d == lane (validity applied post-loop)
        unsigned vmask = 0u;   // valid bits, built on lane 0 only

#pragma unroll
        for (int d = 0; d < kD; d++) {
            float dep = __shfl_sync(FULL, dep_lane, d);
            float X = fmaf(rx, dep, trx);
            float Y = fmaf(ry, dep, try_);
            float Z = fmaf(rz, dep, trz);
            if (Z == 0.f) Z = 1e-9f;
            float rZ = __fdividef(1.f, Z);
            float px = X * rZ, py = Y * rZ;
            // clamp to avoid int overflow; preserves in/out-of-bounds semantics
            px = fminf(fmaxf(px, -4.f), (float)kW + 4.f);
            py = fminf(fmaxf(py, -4.f), (float)kH + 4.f);
            float x0f = floorf(px), y0f = floorf(py);
            float wx = px - x0f, wy = py - y0f;
            int x0 = (int)x0f, y0 = (int)y0f;
            bool bx0 = (unsigned)x0 < (unsigned)kW;
            bool bx1 = (unsigned)(x0 + 1) < (unsigned)kW;
            bool by0 = (unsigned)y0 < (unsigned)kH;
            bool by1 = (unsigned)(y0 + 1) < (unsigned)kH;
            int base = y0 * (kW * kC) + x0 * kC;
            float owx = 1.f - wx, owy = 1.f - wy;
            float acc = 0.f;
            if (bx0 && by0) acc = fmaf(owx * owy, srcL[base], acc);
            if (bx1 && by0) acc = fmaf(wx  * owy, srcL[base + kC], acc);
            if (bx0 && by1) acc = fmaf(owx * wy,  srcL[base + kW*kC], acc);
            if (bx1 && by1) acc = fmaf(wx  * wy,  srcL[base + kW*kC + kC], acc);
            // validity bit on lane 0 only (channel 0); broadcast after the loop
            if (lane == 0) vmask |= (acc != 0.f) ? (1u << d) : 0u;
            // grouped correlation: prefolded mean over 4 channels in my group
            float prod = acc * refc4;
            prod += __shfl_xor_sync(FULL, prod, 1);
            prod += __shfl_xor_sync(FULL, prod, 2);
            // cfd = prod (group value). Two group trees:
            //   ts = Sum_g cfd (softmax logit), qv = Sum_g wreg_g*cfd (attn numerator)
            float ts = prod;
            float qv = prod * wreg_g;
            ts += __shfl_xor_sync(FULL, ts, 4);
            qv += __shfl_xor_sync(FULL, qv, 4);
            ts += __shfl_xor_sync(FULL, ts, 8);
            qv += __shfl_xor_sync(FULL, qv, 8);
            ts += __shfl_xor_sync(FULL, ts, 16);
            qv += __shfl_xor_sync(FULL, qv, 16);
            float e = __expf(ts);     // logits O(+-10): no max-subtract needed
            den += e;
            if (lane == d) {
                my_e = e;
                P = e * qv;
            }
        }
        vmask = __shfl_sync(FULL, vmask, 0);

        float factor = 0.17677669529663687f / den;  // (1/sqrt(C)) / den  (precise)
        cws_lane += my_e * factor;
        float mybit = (float)((vmask >> lane) & 1u);
        sumw_lane += srcw * mybit;
        nv_lane += mybit;
        Lacc = fmaf(P * mybit, factor * srcw, Lacc);
        // sims[s] = mean over D of src_w * valid
        if (lane == 0)
            out[OFF_WT + s * kHW + p] = srcw * (float)__popc(vmask) * (1.f / kD);
    }

    // ---------------- final per-pixel stage ----------------
    float hmin = dec_f(g_min_enc), hmax = dec_f(g_max_enc);
    float nh_lane = (dep_lane - hmin) / (hmax - hmin);

    // qv tree summed over 32 lanes = 4x the 8-group sum -> *0.25
    // precise two-step division matching reference (/sum_weight then /cor_weight_sum)
    float logit_lane = (Lacc * 0.25f / sumw_lane) / cws_lane + nh_lane;

    // softmax over depth (precise; once per pixel)
    float m2 = logit_lane;
#pragma unroll
    for (int off = 16; off > 0; off >>= 1)
        m2 = fmaxf(m2, __shfl_xor_sync(FULL, m2, off));
    float e2 = expf(logit_lane - m2);
    float den2 = e2;
#pragma unroll
    for (int off = 16; off > 0; off >>= 1)
        den2 += __shfl_xor_sync(FULL, den2, off);
    float aw = e2 / den2;
    out[OFF_ATTN + lane * kHW + p] = aw;
    out[OFF_NV + lane * kHW + p] = nv_lane;

    // argmax (first index on tie, matching jnp.argmax)
    float bv = aw; int bi = lane;
#pragma unroll
    for (int off = 16; off > 0; off >>= 1) {
        float ov = __shfl_xor_sync(FULL, bv, off);
        int oi = __shfl_xor_sync(FULL, bi, off);
        if (ov > bv || (ov == bv && oi < bi)) { bv = ov; bi = oi; }
    }
    float depth = __shfl_sync(FULL, dep_lane, bi);
    float d0 = __shfl_sync(FULL, dep_lane, 0);
    float d1 = __shfl_sync(FULL, dep_lane, 1);
    float sw0 = __shfl_sync(FULL, sumw_lane, 0);
    if (lane == 0) {
        out[OFF_DEPTH + p] = depth;
        out[OFF_CONF + p] = bv;
        out[OFF_SW + p] = sw0 * 0.25f;   // / nsrc
        float itv = d1 - d0;
        out[OFF_MIN + p] = depth - itv;
        out[OFF_MAX + p] = depth + itv;
    }
    if (lane < 3) {
        out[OFF_EN + lane * kHW + p] =
            w_norm[lane*3+0]*np0 + w_norm[lane*3+1]*np1 + w_norm[lane*3+2]*np2;
    }
}

// ---------------------------------------------------------------------------
extern "C" void kernel_launch(void* const* d_in, const int* in_sizes, int n_in,
                              void* d_out, int out_size) {
    const float* ref   = (const float*)d_in[0];  // (1,32,192,192)
    const float* src   = (const float*)d_in[1];  // (4,1,32,192,192)
    const float* rotn  = (const float*)d_in[2];  // (1,5,3,3)
    const float* normp = (const float*)d_in[3];  // (1,3,192,192)
    const float* projm = (const float*)d_in[4];  // (1,5,2,4,4)
    const float* dhypo = (const float*)d_in[5];  // (1,32,192,192)
    const float* wreg  = (const float*)d_in[6];  // (8,)
    const float* wnorm = (const float*)d_in[7];  // (3,3)
    float* out = (float*)d_out;

    setup_kernel<<<1, 1>>>(rotn, projm);
    dim3 tb(32, 32);
    dim3 tg(kW / 32, kH, 5);
    transpose_kernel<<<tg, tb>>>(ref, src);
    minmax_kernel<<<256, 256>>>(dhypo);
    main_kernel<<<kHW / 4, 128>>>(normp, dhypo, wreg, wnorm, out);
}